// round 14
// baseline (speedup 1.0000x reference)
#include <cuda_runtime.h>
#include <cstdint>

// Problem constants
#define CB    128
#define HH    56
#define WW    56
#define NPIX  3136
#define BATCH 8
#define NTOT  25088        // BATCH * NPIX
#define KTOT  1152         // CB * 9
#define OUTC  128

// Scratch
__device__ float g_off4[4][BATCH * 18 * NPIX];  // offset conv partial sums (fp32)
__device__ float g_wt32[(size_t)OUTC * KTOT];   // tf32 weights, k' = n*128 + c

__device__ __forceinline__ float to_tf32(float f) {
    uint32_t u;
    asm("cvt.rna.tf32.f32 %0, %1;" : "=r"(u) : "f"(f));
    return __uint_as_float(u);
}
__device__ __forceinline__ uint32_t smem_u32(const void* p) {
    uint32_t a;
    asm("{ .reg .u64 t; cvta.to.shared.u64 t, %1; cvt.u32.u64 %0, t; }" : "=r"(a) : "l"(p));
    return a;
}
#define CP_ASYNC_CA(dst, src) \
    asm volatile("cp.async.ca.shared.global [%0], [%1], 16;" :: "r"(dst), "l"(src))
#define CP_COMMIT() asm volatile("cp.async.commit_group;" ::: "memory")
#define CP_WAIT(n)  asm volatile("cp.async.wait_group %0;" :: "n"(n) : "memory")
#define LDMATRIX_X4(r, addr) \
    asm volatile("ldmatrix.sync.aligned.m8n8.x4.shared.b16 {%0,%1,%2,%3}, [%4];" \
        : "=r"((r)[0]), "=r"((r)[1]), "=r"((r)[2]), "=r"((r)[3]) : "r"(addr))

// ---------------------------------------------------------------------------
// Kernel 1: offset conv FP32 (quarter-split) + inline weight prep.
// 1792 blocks x 128 threads; thread i < 147456 also preps one tf32 weight.
// ---------------------------------------------------------------------------
#define OC_CCH 16

__global__ __launch_bounds__(128) void offset_conv_kernel(
        const float* __restrict__ x,
        const float* __restrict__ w,
        const float* __restrict__ bias,
        const float* __restrict__ cw) {
    __shared__ float xs[OC_CCH][3][60];
    __shared__ float ws[OC_CCH][18][9];

    int blk  = blockIdx.x;
    int tid  = threadIdx.x;

    // inline weight prep: k permute c*9+n -> n*128+c, tf32 round
    {
        int i = blk * 128 + tid;
        if (i < OUTC * KTOT) {
            int o = i / KTOT;
            int r = i % KTOT;
            int c = r / 9;
            int n = r % 9;
            g_wt32[(size_t)o * KTOT + n * 128 + c] = to_tf32(__ldg(cw + i));
        }
    }

    int q    = blk & 3;
    int by   = blk >> 2;
    int b    = by / HH;
    int y    = by % HH;
    int j     = tid / 7;
    int strip = tid % 7;
    bool active = tid < 126;

    for (int e = tid; e < OC_CCH * 3; e += 128) {
        int cc = e / 3, r = e % 3;
        xs[cc][r][0] = 0.f; xs[cc][r][57] = 0.f;
        xs[cc][r][58] = 0.f; xs[cc][r][59] = 0.f;
    }

    float acc[8];
    #pragma unroll
    for (int i = 0; i < 8; ++i) acc[i] = 0.f;

    const float* xb = x + (size_t)b * CB * NPIX;
    int cbeg = q * 32;

    for (int c0 = cbeg; c0 < cbeg + 32; c0 += OC_CCH) {
        __syncthreads();
        for (int e = tid; e < OC_CCH * 3 * WW; e += 128) {
            int cc  = e / (3 * WW);
            int r2  = e % (3 * WW);
            int r   = r2 / WW;
            int col = r2 % WW;
            int yy  = y - 1 + r;
            float v = 0.f;
            if (yy >= 0 && yy < HH)
                v = __ldg(xb + (size_t)(c0 + cc) * NPIX + yy * WW + col);
            xs[cc][r][col + 1] = v;
        }
        for (int e = tid; e < OC_CCH * 162; e += 128) {
            int cc = e / 162;
            int r2 = e % 162;
            ws[cc][r2 / 9][r2 % 9] = __ldg(w + (r2 / 9) * KTOT + (c0 + cc) * 9 + (r2 % 9));
        }
        __syncthreads();

        if (active) {
            #pragma unroll 4
            for (int cc = 0; cc < OC_CCH; ++cc) {
                float wr[9];
                #pragma unroll
                for (int t = 0; t < 9; ++t) wr[t] = ws[cc][j][t];
                #pragma unroll
                for (int ky = 0; ky < 3; ++ky) {
                    float rv[10];
                    #pragma unroll
                    for (int i = 0; i < 10; ++i) rv[i] = xs[cc][ky][strip * 8 + i];
                    #pragma unroll
                    for (int kx = 0; kx < 3; ++kx) {
                        float wv = wr[ky * 3 + kx];
                        #pragma unroll
                        for (int i = 0; i < 8; ++i)
                            acc[i] = fmaf(wv, rv[i + kx], acc[i]);
                    }
                }
            }
        }
    }

    if (active) {
        float bj = (q == 0) ? __ldg(bias + j) : 0.f;
        float* op = g_off4[q] + (size_t)(b * 18 + j) * NPIX + y * WW + strip * 8;
        #pragma unroll
        for (int i = 0; i < 8; ++i) op[i] = acc[i] + bj;
    }
}

// ---------------------------------------------------------------------------
// Kernel 2: FUSED sample + tf32 mma GEMM, BK=32 (36 iters).
// SPILL TEST: __launch_bounds__(256, 2) -> 128-reg cap (was 83 with ,3).
// Dynamic smem layout (64512 B): wsm/osm tables + 2-stage As + 2-stage Bs.
// Pipeline per iter: build B(t) -> CP_WAIT(0) -> sync -> issue A(t+1) -> 4x mma.
// ---------------------------------------------------------------------------
#define ROWF 36
#define NCHUNK2 36
#define OFF_WSM 0u
#define OFF_OSM 4608u
#define OFF_AS  9216u
#define OFF_BS  46080u
#define ASTG (128u * ROWF * 4u)    // 18432 B per A stage
#define BSTG (64u * ROWF * 4u)     // 9216 B per B stage
#define SMEM_DYN (OFF_BS + 2u * BSTG)   // 64512

__global__ __launch_bounds__(256, 2) void fused_gemm_kernel(
        const float* __restrict__ x, float* __restrict__ out) {
    extern __shared__ __align__(16) unsigned char dyn[];
    float2* wsm = (float2*)(dyn + OFF_WSM);   // [64][9]
    int2*   osm = (int2*)(dyn + OFF_OSM);     // [64][9]

    int tid  = threadIdx.x;
    int wid  = tid >> 5;
    int lid  = tid & 31;
    int gid  = lid >> 2;
    int tig  = lid & 3;
    int warp_m = wid & 3;
    int warp_n = wid >> 2;

    int b    = blockIdx.x / 49;
    int tile = blockIdx.x % 49;
    int px0  = tile * 64;

    const float* xb = x + (size_t)b * CB * NPIX;

    // ---------------- Phase A: merged bilinear tables ----------------
    for (int e = tid; e < 576; e += 256) {
        int np_l = e / 9, n = e % 9;
        int pix = px0 + np_l;
        int y = pix / WW, xw = pix % WW;

        size_t iy = (size_t)(b * 18 + n) * NPIX + pix;
        size_t ix = (size_t)(b * 18 + n + 9) * NPIX + pix;
        float off_y = g_off4[0][iy] + g_off4[1][iy] + g_off4[2][iy] + g_off4[3][iy];
        float off_x = g_off4[0][ix] + g_off4[1][ix] + g_off4[2][ix] + g_off4[3][ix];

        float p_y = (float)(y + n / 3) + off_y;
        float p_x = (float)(xw + n % 3) + off_x;

        float qy = floorf(p_y), qx = floorf(p_x);
        float qlt_y = fminf(fmaxf(qy, 0.f), 57.f);
        float qlt_x = fminf(fmaxf(qx, 0.f), 57.f);
        float qrb_y = fminf(fmaxf(qy + 1.f, 0.f), 57.f);
        float qrb_x = fminf(fmaxf(qx + 1.f, 0.f), 57.f);
        float py = fminf(fmaxf(p_y, 0.f), 57.f);
        float px = fminf(fmaxf(p_x, 0.f), 57.f);

        float g_lt = (1.f - (py - qlt_y)) * truncf(1.f - (px - qlt_x));
        float g_rb = (1.f - (qrb_y - py)) * truncf(1.f - (qrb_x - px));
        float g_lb = (1.f - (py - qlt_y)) * (1.f - (qrb_x - px));
        float g_rt = (1.f - (qrb_y - py)) * (1.f - (px - qlt_x));

        int iy_lt = (int)qlt_y, ix_lt = (int)qlt_x;
        int iy_rb = (int)qrb_y, ix_rb = (int)qrb_x;

        int o0 = (iy_lt - 1) * WW + (ix_lt - 1);
        int o1 = (iy_rb - 1) * WW + (ix_rb - 1);
        int o2 = (iy_lt - 1) * WW + (ix_rb - 1);
        int o3 = (iy_rb - 1) * WW + (ix_lt - 1);

        bool vy_lt = (iy_lt >= 1) && (iy_lt <= 56);
        bool vx_lt = (ix_lt >= 1) && (ix_lt <= 56);
        bool vy_rb = (iy_rb >= 1) && (iy_rb <= 56);
        bool vx_rb = (ix_rb >= 1) && (ix_rb <= 56);

        float w0 = (vy_lt && vx_lt) ? g_lt : 0.f;
        float w1 = (vy_rb && vx_rb) ? g_rb : 0.f;
        float w2 = (vy_lt && vx_rb) ? g_lb : 0.f;
        float w3 = (vy_rb && vx_lt) ? g_rt : 0.f;

        float wA, wB; int oA, oB;
        if (o0 == o2)        { wA = w0 + w2; oA = o0; }
        else if (w0 != 0.f)  { wA = w0;      oA = o0; }
        else                 { wA = w2;      oA = o2; }
        if (wA == 0.f) oA = 0;
        if (o1 == o3)        { wB = w1 + w3; oB = o1; }
        else if (w1 != 0.f)  { wB = w1;      oB = o1; }
        else                 { wB = w3;      oB = o3; }
        if (wB == 0.f) oB = 0;

        wsm[np_l * 9 + n] = make_float2(wA, wB);
        osm[np_l * 9 + n] = make_int2(oA, oB);
    }

    // A copy addressing: 4 x cp.async(16B) per thread per chunk (128x32 floats)
    int arow = tid >> 3;            // 0..31 (+32*i)
    int acol = (tid & 7) * 4;       // 0..28
    const float* asrcT = g_wt32 + (size_t)arow * KTOT + acol;
    uint32_t smb  = smem_u32(dyn);
    uint32_t adstT = smb + OFF_AS + (uint32_t)(arow * ROWF + acol) * 4u;

    // ldmatrix lane addresses (bytes), row stride = ROWF*4 = 144
    uint32_t aAddr = smb + OFF_AS
                   + (uint32_t)((warp_m * 32 + (lid & 15)) * ROWF * 4)
                   + (uint32_t)((lid >> 4) << 4);
    uint32_t bAddr0 = smb + OFF_BS
                    + (uint32_t)((warp_n * 32 + (lid & 7) + ((lid >> 4) << 3)) * ROWF * 4)
                    + (uint32_t)(((lid >> 3) & 1) << 4);
    uint32_t bAddr1 = bAddr0 + 16u * ROWF * 4u;

    // B build addressing: pixel fixed per thread, channel group = tid>>6 (8 ch)
    int bpx  = tid & 63;
    int bcg  = tid >> 6;

    float acc[2][4][4];
    #pragma unroll
    for (int mt = 0; mt < 2; ++mt)
        #pragma unroll
        for (int nt = 0; nt < 4; ++nt)
            #pragma unroll
            for (int r = 0; r < 4; ++r) acc[mt][nt][r] = 0.f;

    // prologue: A chunk 0 into stage 0
    #pragma unroll
    for (int i = 0; i < 4; ++i)
        CP_ASYNC_CA(adstT + (uint32_t)(i * 32 * ROWF) * 4u, asrcT + (size_t)i * 32 * KTOT);
    CP_COMMIT();
    __syncthreads();    // tables ready

    for (int t = 0; t < NCHUNK2; ++t) {
        int buf = t & 1;

        // build B tile: n = t/4, channels (t%4)*32 + bcg*8 .. +7 for my pixel.
        {
            int n  = t >> 2;
            int c0 = (t & 3) * 32 + bcg * 8;
            float2 wq = wsm[bpx * 9 + n];
            int2   oq = osm[bpx * 9 + n];
            const float* xc = xb + (size_t)c0 * NPIX;
            float v[8];
            #pragma unroll
            for (int i = 0; i < 8; ++i) {
                const float* xi = xc + (size_t)i * NPIX;
                v[i] = to_tf32(fmaf(wq.y, __ldg(xi + oq.y), wq.x * __ldg(xi + oq.x)));
            }
            float* brow = (float*)(dyn + OFF_BS + (uint32_t)buf * BSTG) + bpx * ROWF + bcg * 8;
            *(float4*)(brow)     = make_float4(v[0], v[1], v[2], v[3]);
            *(float4*)(brow + 4) = make_float4(v[4], v[5], v[6], v[7]);
        }

        CP_WAIT(0);          // A chunk t landed (issued one iteration ago)
        __syncthreads();

        // A prefetch AFTER the barrier (WAR-safe vs iter t-1 readers)
        if (t + 1 < NCHUNK2) {
            uint32_t so = (uint32_t)((t + 1) & 1) * ASTG;
            const float* src = asrcT + (size_t)(t + 1) * 32;
            #pragma unroll
            for (int i = 0; i < 4; ++i)
                CP_ASYNC_CA(adstT + so + (uint32_t)(i * 32 * ROWF) * 4u,
                            src + (size_t)i * 32 * KTOT);
            CP_COMMIT();
        }

        uint32_t aoff = (uint32_t)buf * ASTG;
        uint32_t boff = (uint32_t)buf * BSTG;

        #pragma unroll
        for (int ks = 0; ks < 4; ++ks) {
            uint32_t koff = (uint32_t)ks * 32u;   // 8 floats per k-step
            uint32_t a0r[4], a1r[4], b0r[4], b1r[4];
            LDMATRIX_X4(a0r, aAddr + aoff + koff);
            LDMATRIX_X4(a1r, aAddr + aoff + koff + 16u * ROWF * 4u);
            LDMATRIX_X4(b0r, bAddr0 + boff + koff);
            LDMATRIX_X4(b1r, bAddr1 + boff + koff);

            const uint32_t* afr[2] = {a0r, a1r};
            uint32_t bfr[4][2] = {{b0r[0], b0r[1]}, {b0r[2], b0r[3]},
                                  {b1r[0], b1r[1]}, {b1r[2], b1r[3]}};
            #pragma unroll
            for (int mt = 0; mt < 2; ++mt)
                #pragma unroll
                for (int nt = 0; nt < 4; ++nt) {
                    asm volatile(
                        "mma.sync.aligned.m16n8k8.row.col.f32.tf32.tf32.f32 "
                        "{%0,%1,%2,%3}, {%4,%5,%6,%7}, {%8,%9}, {%0,%1,%2,%3};"
                        : "+f"(acc[mt][nt][0]), "+f"(acc[mt][nt][1]),
                          "+f"(acc[mt][nt][2]), "+f"(acc[mt][nt][3])
                        : "r"(afr[mt][0]), "r"(afr[mt][1]), "r"(afr[mt][2]), "r"(afr[mt][3]),
                          "r"(bfr[nt][0]), "r"(bfr[nt][1]));
                }
        }
    }

    // epilogue
    int rA = warp_m * 32 + gid;
    #pragma unroll
    for (int mt = 0; mt < 2; ++mt) {
        #pragma unroll
        for (int half = 0; half < 2; ++half) {
            int o = rA + mt * 16 + half * 8;
            float* po = out + ((size_t)b * OUTC + o) * NPIX + px0;
            #pragma unroll
            for (int nt = 0; nt < 4; ++nt) {
                int col = warp_n * 32 + nt * 8 + 2 * tig;
                float2 v = make_float2(acc[mt][nt][half * 2], acc[mt][nt][half * 2 + 1]);
                *(float2*)(po + col) = v;
            }
        }
    }
}

// ---------------------------------------------------------------------------
extern "C" void kernel_launch(void* const* d_in, const int* in_sizes, int n_in,
                              void* d_out, int out_size) {
    const float* x  = (const float*)d_in[0];
    const float* ow = (const float*)d_in[1];
    const float* ob = (const float*)d_in[2];
    const float* cw = (const float*)d_in[3];
    float* out = (float*)d_out;

    static bool attr_done = false;
    if (!attr_done) {
        cudaFuncSetAttribute(fused_gemm_kernel,
                             cudaFuncAttributeMaxDynamicSharedMemorySize, SMEM_DYN);
        attr_done = true;
    }

    offset_conv_kernel<<<BATCH * HH * 4, 128>>>(x, ow, ob, cw);
    fused_gemm_kernel<<<NTOT / 64, 256, SMEM_DYN>>>(x, out);
}

// round 15
// speedup vs baseline: 1.0019x; 1.0019x over previous
#include <cuda_runtime.h>
#include <cstdint>

// Problem constants
#define CB    128
#define HH    56
#define WW    56
#define NPIX  3136
#define BATCH 8
#define NTOT  25088        // BATCH * NPIX
#define KTOT  1152         // CB * 9
#define OUTC  128

// Scratch
__device__ float g_off4[4][BATCH * 18 * NPIX];  // offset conv partial sums (fp32)
__device__ float g_wt32[(size_t)OUTC * KTOT];   // tf32 weights, k' = n*128 + c

__device__ __forceinline__ float to_tf32(float f) {
    uint32_t u;
    asm("cvt.rna.tf32.f32 %0, %1;" : "=r"(u) : "f"(f));
    return __uint_as_float(u);
}
__device__ __forceinline__ uint32_t smem_u32(const void* p) {
    uint32_t a;
    asm("{ .reg .u64 t; cvta.to.shared.u64 t, %1; cvt.u32.u64 %0, t; }" : "=r"(a) : "l"(p));
    return a;
}
#define CP_ASYNC_CA(dst, src) \
    asm volatile("cp.async.ca.shared.global [%0], [%1], 16;" :: "r"(dst), "l"(src))
#define CP_COMMIT() asm volatile("cp.async.commit_group;" ::: "memory")
#define CP_WAIT(n)  asm volatile("cp.async.wait_group %0;" :: "n"(n) : "memory")
#define LDMATRIX_X4(r, addr) \
    asm volatile("ldmatrix.sync.aligned.m8n8.x4.shared.b16 {%0,%1,%2,%3}, [%4];" \
        : "=r"((r)[0]), "=r"((r)[1]), "=r"((r)[2]), "=r"((r)[3]) : "r"(addr))

// ---------------------------------------------------------------------------
// Kernel 1: offset conv FP32 (quarter-split) + inline weight prep.
// 1792 blocks x 128 threads. Inner loop vectorized: 12 LDS.128 per channel
// (3 float4 x 3 ky rows + 3 float4 weights) instead of 39 scalar LDS.
// ---------------------------------------------------------------------------
#define OC_CCH 16

__global__ __launch_bounds__(128) void offset_conv_kernel(
        const float* __restrict__ x,
        const float* __restrict__ w,
        const float* __restrict__ bias,
        const float* __restrict__ cw) {
    __shared__ __align__(16) float xs[OC_CCH][3][60];   // 11520 B, rows 240B
    __shared__ __align__(16) float ws[OC_CCH][18][12];  // 13824 B, rows 48B

    int blk  = blockIdx.x;
    int tid  = threadIdx.x;

    // inline weight prep: k permute c*9+n -> n*128+c, tf32 round
    {
        int i = blk * 128 + tid;
        if (i < OUTC * KTOT) {
            int o = i / KTOT;
            int r = i % KTOT;
            int c = r / 9;
            int n = r % 9;
            g_wt32[(size_t)o * KTOT + n * 128 + c] = to_tf32(__ldg(cw + i));
        }
    }

    int q    = blk & 3;
    int by   = blk >> 2;
    int b    = by / HH;
    int y    = by % HH;
    int j     = tid / 7;
    int strip = tid % 7;
    bool active = tid < 126;

    for (int e = tid; e < OC_CCH * 3; e += 128) {
        int cc = e / 3, r = e % 3;
        xs[cc][r][0] = 0.f; xs[cc][r][57] = 0.f;
        xs[cc][r][58] = 0.f; xs[cc][r][59] = 0.f;
    }

    float acc[8];
    #pragma unroll
    for (int i = 0; i < 8; ++i) acc[i] = 0.f;

    const float* xb = x + (size_t)b * CB * NPIX;
    int cbeg = q * 32;

    for (int c0 = cbeg; c0 < cbeg + 32; c0 += OC_CCH) {
        __syncthreads();
        for (int e = tid; e < OC_CCH * 3 * WW; e += 128) {
            int cc  = e / (3 * WW);
            int r2  = e % (3 * WW);
            int r   = r2 / WW;
            int col = r2 % WW;
            int yy  = y - 1 + r;
            float v = 0.f;
            if (yy >= 0 && yy < HH)
                v = __ldg(xb + (size_t)(c0 + cc) * NPIX + yy * WW + col);
            xs[cc][r][col + 1] = v;
        }
        for (int e = tid; e < OC_CCH * 162; e += 128) {
            int cc = e / 162;
            int r2 = e % 162;
            ws[cc][r2 / 9][r2 % 9] = __ldg(w + (r2 / 9) * KTOT + (c0 + cc) * 9 + (r2 % 9));
        }
        __syncthreads();

        if (active) {
            #pragma unroll 2
            for (int cc = 0; cc < OC_CCH; ++cc) {
                float wr[12];
                {
                    float4 w0 = *(const float4*)&ws[cc][j][0];
                    float4 w1 = *(const float4*)&ws[cc][j][4];
                    float4 w2 = *(const float4*)&ws[cc][j][8];
                    wr[0] = w0.x; wr[1] = w0.y; wr[2]  = w0.z; wr[3]  = w0.w;
                    wr[4] = w1.x; wr[5] = w1.y; wr[6]  = w1.z; wr[7]  = w1.w;
                    wr[8] = w2.x; wr[9] = w2.y; wr[10] = w2.z; wr[11] = w2.w;
                }
                #pragma unroll
                for (int ky = 0; ky < 3; ++ky) {
                    const float* rp = &xs[cc][ky][strip * 8];
                    float4 r0 = *(const float4*)(rp);
                    float4 r1 = *(const float4*)(rp + 4);
                    float4 r2 = *(const float4*)(rp + 8);
                    float rv[12] = {r0.x, r0.y, r0.z, r0.w,
                                    r1.x, r1.y, r1.z, r1.w,
                                    r2.x, r2.y, r2.z, r2.w};
                    #pragma unroll
                    for (int kx = 0; kx < 3; ++kx) {
                        float wv = wr[ky * 3 + kx];
                        #pragma unroll
                        for (int i = 0; i < 8; ++i)
                            acc[i] = fmaf(wv, rv[i + kx], acc[i]);
                    }
                }
            }
        }
    }

    if (active) {
        float bj = (q == 0) ? __ldg(bias + j) : 0.f;
        float* op = g_off4[q] + (size_t)(b * 18 + j) * NPIX + y * WW + strip * 8;
        #pragma unroll
        for (int i = 0; i < 8; ++i) op[i] = acc[i] + bj;
    }
}

// ---------------------------------------------------------------------------
// Kernel 2: FUSED sample + tf32 mma GEMM, BK=32 (36 iters). UNCHANGED (R14,
// measured 86.6us, regs=94, no spills at __launch_bounds__(256,2)).
// ---------------------------------------------------------------------------
#define ROWF 36
#define NCHUNK2 36
#define OFF_WSM 0u
#define OFF_OSM 4608u
#define OFF_AS  9216u
#define OFF_BS  46080u
#define ASTG (128u * ROWF * 4u)
#define BSTG (64u * ROWF * 4u)
#define SMEM_DYN (OFF_BS + 2u * BSTG)   // 64512

__global__ __launch_bounds__(256, 2) void fused_gemm_kernel(
        const float* __restrict__ x, float* __restrict__ out) {
    extern __shared__ __align__(16) unsigned char dyn[];
    float2* wsm = (float2*)(dyn + OFF_WSM);
    int2*   osm = (int2*)(dyn + OFF_OSM);

    int tid  = threadIdx.x;
    int wid  = tid >> 5;
    int lid  = tid & 31;
    int gid  = lid >> 2;
    int tig  = lid & 3;
    int warp_m = wid & 3;
    int warp_n = wid >> 2;

    int b    = blockIdx.x / 49;
    int tile = blockIdx.x % 49;
    int px0  = tile * 64;

    const float* xb = x + (size_t)b * CB * NPIX;

    // Phase A: merged bilinear tables
    for (int e = tid; e < 576; e += 256) {
        int np_l = e / 9, n = e % 9;
        int pix = px0 + np_l;
        int y = pix / WW, xw = pix % WW;

        size_t iy = (size_t)(b * 18 + n) * NPIX + pix;
        size_t ix = (size_t)(b * 18 + n + 9) * NPIX + pix;
        float off_y = g_off4[0][iy] + g_off4[1][iy] + g_off4[2][iy] + g_off4[3][iy];
        float off_x = g_off4[0][ix] + g_off4[1][ix] + g_off4[2][ix] + g_off4[3][ix];

        float p_y = (float)(y + n / 3) + off_y;
        float p_x = (float)(xw + n % 3) + off_x;

        float qy = floorf(p_y), qx = floorf(p_x);
        float qlt_y = fminf(fmaxf(qy, 0.f), 57.f);
        float qlt_x = fminf(fmaxf(qx, 0.f), 57.f);
        float qrb_y = fminf(fmaxf(qy + 1.f, 0.f), 57.f);
        float qrb_x = fminf(fmaxf(qx + 1.f, 0.f), 57.f);
        float py = fminf(fmaxf(p_y, 0.f), 57.f);
        float px = fminf(fmaxf(p_x, 0.f), 57.f);

        float g_lt = (1.f - (py - qlt_y)) * truncf(1.f - (px - qlt_x));
        float g_rb = (1.f - (qrb_y - py)) * truncf(1.f - (qrb_x - px));
        float g_lb = (1.f - (py - qlt_y)) * (1.f - (qrb_x - px));
        float g_rt = (1.f - (qrb_y - py)) * (1.f - (px - qlt_x));

        int iy_lt = (int)qlt_y, ix_lt = (int)qlt_x;
        int iy_rb = (int)qrb_y, ix_rb = (int)qrb_x;

        int o0 = (iy_lt - 1) * WW + (ix_lt - 1);
        int o1 = (iy_rb - 1) * WW + (ix_rb - 1);
        int o2 = (iy_lt - 1) * WW + (ix_rb - 1);
        int o3 = (iy_rb - 1) * WW + (ix_lt - 1);

        bool vy_lt = (iy_lt >= 1) && (iy_lt <= 56);
        bool vx_lt = (ix_lt >= 1) && (ix_lt <= 56);
        bool vy_rb = (iy_rb >= 1) && (iy_rb <= 56);
        bool vx_rb = (ix_rb >= 1) && (ix_rb <= 56);

        float w0 = (vy_lt && vx_lt) ? g_lt : 0.f;
        float w1 = (vy_rb && vx_rb) ? g_rb : 0.f;
        float w2 = (vy_lt && vx_rb) ? g_lb : 0.f;
        float w3 = (vy_rb && vx_lt) ? g_rt : 0.f;

        float wA, wB; int oA, oB;
        if (o0 == o2)        { wA = w0 + w2; oA = o0; }
        else if (w0 != 0.f)  { wA = w0;      oA = o0; }
        else                 { wA = w2;      oA = o2; }
        if (wA == 0.f) oA = 0;
        if (o1 == o3)        { wB = w1 + w3; oB = o1; }
        else if (w1 != 0.f)  { wB = w1;      oB = o1; }
        else                 { wB = w3;      oB = o3; }
        if (wB == 0.f) oB = 0;

        wsm[np_l * 9 + n] = make_float2(wA, wB);
        osm[np_l * 9 + n] = make_int2(oA, oB);
    }

    int arow = tid >> 3;
    int acol = (tid & 7) * 4;
    const float* asrcT = g_wt32 + (size_t)arow * KTOT + acol;
    uint32_t smb  = smem_u32(dyn);
    uint32_t adstT = smb + OFF_AS + (uint32_t)(arow * ROWF + acol) * 4u;

    uint32_t aAddr = smb + OFF_AS
                   + (uint32_t)((warp_m * 32 + (lid & 15)) * ROWF * 4)
                   + (uint32_t)((lid >> 4) << 4);
    uint32_t bAddr0 = smb + OFF_BS
                    + (uint32_t)((warp_n * 32 + (lid & 7) + ((lid >> 4) << 3)) * ROWF * 4)
                    + (uint32_t)(((lid >> 3) & 1) << 4);
    uint32_t bAddr1 = bAddr0 + 16u * ROWF * 4u;

    int bpx  = tid & 63;
    int bcg  = tid >> 6;

    float acc[2][4][4];
    #pragma unroll
    for (int mt = 0; mt < 2; ++mt)
        #pragma unroll
        for (int nt = 0; nt < 4; ++nt)
            #pragma unroll
            for (int r = 0; r < 4; ++r) acc[mt][nt][r] = 0.f;

    #pragma unroll
    for (int i = 0; i < 4; ++i)
        CP_ASYNC_CA(adstT + (uint32_t)(i * 32 * ROWF) * 4u, asrcT + (size_t)i * 32 * KTOT);
    CP_COMMIT();
    __syncthreads();

    for (int t = 0; t < NCHUNK2; ++t) {
        int buf = t & 1;

        {
            int n  = t >> 2;
            int c0 = (t & 3) * 32 + bcg * 8;
            float2 wq = wsm[bpx * 9 + n];
            int2   oq = osm[bpx * 9 + n];
            const float* xc = xb + (size_t)c0 * NPIX;
            float v[8];
            #pragma unroll
            for (int i = 0; i < 8; ++i) {
                const float* xi = xc + (size_t)i * NPIX;
                v[i] = to_tf32(fmaf(wq.y, __ldg(xi + oq.y), wq.x * __ldg(xi + oq.x)));
            }
            float* brow = (float*)(dyn + OFF_BS + (uint32_t)buf * BSTG) + bpx * ROWF + bcg * 8;
            *(float4*)(brow)     = make_float4(v[0], v[1], v[2], v[3]);
            *(float4*)(brow + 4) = make_float4(v[4], v[5], v[6], v[7]);
        }

        CP_WAIT(0);
        __syncthreads();

        if (t + 1 < NCHUNK2) {
            uint32_t so = (uint32_t)((t + 1) & 1) * ASTG;
            const float* src = asrcT + (size_t)(t + 1) * 32;
            #pragma unroll
            for (int i = 0; i < 4; ++i)
                CP_ASYNC_CA(adstT + so + (uint32_t)(i * 32 * ROWF) * 4u,
                            src + (size_t)i * 32 * KTOT);
            CP_COMMIT();
        }

        uint32_t aoff = (uint32_t)buf * ASTG;
        uint32_t boff = (uint32_t)buf * BSTG;

        #pragma unroll
        for (int ks = 0; ks < 4; ++ks) {
            uint32_t koff = (uint32_t)ks * 32u;
            uint32_t a0r[4], a1r[4], b0r[4], b1r[4];
            LDMATRIX_X4(a0r, aAddr + aoff + koff);
            LDMATRIX_X4(a1r, aAddr + aoff + koff + 16u * ROWF * 4u);
            LDMATRIX_X4(b0r, bAddr0 + boff + koff);
            LDMATRIX_X4(b1r, bAddr1 + boff + koff);

            const uint32_t* afr[2] = {a0r, a1r};
            uint32_t bfr[4][2] = {{b0r[0], b0r[1]}, {b0r[2], b0r[3]},
                                  {b1r[0], b1r[1]}, {b1r[2], b1r[3]}};
            #pragma unroll
            for (int mt = 0; mt < 2; ++mt)
                #pragma unroll
                for (int nt = 0; nt < 4; ++nt) {
                    asm volatile(
                        "mma.sync.aligned.m16n8k8.row.col.f32.tf32.tf32.f32 "
                        "{%0,%1,%2,%3}, {%4,%5,%6,%7}, {%8,%9}, {%0,%1,%2,%3};"
                        : "+f"(acc[mt][nt][0]), "+f"(acc[mt][nt][1]),
                          "+f"(acc[mt][nt][2]), "+f"(acc[mt][nt][3])
                        : "r"(afr[mt][0]), "r"(afr[mt][1]), "r"(afr[mt][2]), "r"(afr[mt][3]),
                          "r"(bfr[nt][0]), "r"(bfr[nt][1]));
                }
        }
    }

    int rA = warp_m * 32 + gid;
    #pragma unroll
    for (int mt = 0; mt < 2; ++mt) {
        #pragma unroll
        for (int half = 0; half < 2; ++half) {
            int o = rA + mt * 16 + half * 8;
            float* po = out + ((size_t)b * OUTC + o) * NPIX + px0;
            #pragma unroll
            for (int nt = 0; nt < 4; ++nt) {
                int col = warp_n * 32 + nt * 8 + 2 * tig;
                float2 v = make_float2(acc[mt][nt][half * 2], acc[mt][nt][half * 2 + 1]);
                *(float2*)(po + col) = v;
            }
        }
    }
}

// ---------------------------------------------------------------------------
extern "C" void kernel_launch(void* const* d_in, const int* in_sizes, int n_in,
                              void* d_out, int out_size) {
    const float* x  = (const float*)d_in[0];
    const float* ow = (const float*)d_in[1];
    const float* ob = (const float*)d_in[2];
    const float* cw = (const float*)d_in[3];
    float* out = (float*)d_out;

    static bool attr_done = false;
    if (!attr_done) {
        cudaFuncSetAttribute(fused_gemm_kernel,
                             cudaFuncAttributeMaxDynamicSharedMemorySize, SMEM_DYN);
        attr_done = true;
    }

    offset_conv_kernel<<<BATCH * HH * 4, 128>>>(x, ow, ob, cw);
    fused_gemm_kernel<<<NTOT / 64, 256, SMEM_DYN>>>(x, out);
}